// round 6
// baseline (speedup 1.0000x reference)
#include <cuda_runtime.h>
#include <string.h>

// Levinson-Durbin, one thread per batch (B=65536, M=64), f32x2 dot product.
// r kept ONLY in shared, as two reversed copies (one per alignment parity):
//   sA[b][64-c] = r_b[c]   (serves odd-m pair loads + all scalar reads)
//   sB[b][65-c] = r_b[c]   (serves even-m pair loads)
// Descending r-pairs {r[m-j], r[m-j-1]} become one aligned LDS.64, feeding
// fma.rn.f32x2 against register-packed a-pairs aP[t] = {a[2t+1], a[2t+2]}.
// Register state ~80 floats -> no launch_bounds cap games; 6 CTAs/SM (smem
// bound), 12 warps/SM vs R1's 8.

constexpr int M  = 64;
constexpr int NR = M + 1;   // 65
constexpr int BT = 64;      // threads (batches) per block
constexpr int RS = 66;      // floats per shared row: 8B-aligned rows (264B),
                            // and 33 pairs/row (odd) -> LDS.64 conflict-free

__device__ __forceinline__ float2 ffma2(float2 a, float2 b, float2 c) {
    unsigned long long ua, ub, uc, ud;
    memcpy(&ua, &a, 8); memcpy(&ub, &b, 8); memcpy(&uc, &c, 8);
    asm("fma.rn.f32x2 %0, %1, %2, %3;" : "=l"(ud) : "l"(ua), "l"(ub), "l"(uc));
    float2 d; memcpy(&d, &ud, 8); return d;
}

// a[i] accessor into packed pairs (compile-time i after full unroll).
#define A_(i) (((i) & 1) ? aP[((i) - 1) >> 1].x : aP[((i) >> 1) - 1].y)

__global__ __launch_bounds__(BT)
void levdur_kernel(const float* __restrict__ g_r,
                   float* __restrict__ g_out,
                   int nbatch)
{
    __shared__ __align__(16) float sA[BT * RS];   // 16,896 B
    __shared__ __align__(16) float sB[BT * RS];   // 16,896 B
    const int tid = threadIdx.x;
    const long long base  = (long long)blockIdx.x * BT * NR;
    const long long total = (long long)nbatch * NR;

    // Coalesced load; scatter into both reversed copies (stride-1 descending
    // shared writes -> essentially conflict-free; one-time cost).
    #pragma unroll
    for (int i = 0; i < NR; ++i) {
        long long idx = base + (long long)i * BT + tid;
        if (idx < total) {
            float v  = g_r[idx];
            int  loc = i * BT + tid;
            int  b   = loc / NR;
            int  c   = loc - b * NR;
            sA[b * RS + (64 - c)] = v;
            sB[b * RS + (65 - c)] = v;
        }
    }
    __syncthreads();

    const int batch = blockIdx.x * BT + tid;
    const float* Ar = &sA[tid * RS];
    const float* Br = &sB[tid * RS];

    if (batch < nbatch) {
        float2 aP[32];                 // aP[t] = {a[2t+1], a[2t+2]}
        float  E   = Ar[64];           // r[0]
        const float rr1 = Ar[63];      // r[1] (leftover term, reused 32x)

        #pragma unroll
        for (int m = 1; m <= M; ++m) {
            // num = r[m] + sum_{j=1}^{m-1} a[j] * r[m-j]
            // pairs j=2t+1: operand {r[m-j], r[m-j-1]} as one LDS.64.
            float2 acc0 = make_float2(0.f, 0.f);
            float2 acc1 = make_float2(0.f, 0.f);
            if (m & 1) {
                #pragma unroll
                for (int t = 0; t <= (m - 3) / 2; ++t) {
                    float2 rv = *reinterpret_cast<const float2*>(&Ar[64 - m + 2 * t + 1]);
                    if (t & 1) acc1 = ffma2(aP[t], rv, acc1);
                    else       acc0 = ffma2(aP[t], rv, acc0);
                }
            } else {
                #pragma unroll
                for (int t = 0; t <= (m - 4) / 2; ++t) {
                    float2 rv = *reinterpret_cast<const float2*>(&Br[65 - m + 2 * t + 1]);
                    if (t & 1) acc1 = ffma2(aP[t], rv, acc1);
                    else       acc0 = ffma2(aP[t], rv, acc0);
                }
            }
            float num = (acc0.x + acc1.x) + (acc0.y + acc1.y);
            num += Ar[64 - m];                               // + r[m]
            if ((m & 1) == 0 && m >= 2)                      // leftover j=m-1
                num = fmaf(A_(m - 1), rr1, num);

            float k = __fdividef(-num, E);
            E = fmaf(-k * k, E, E);                          // E *= (1 - k^2)

            // a_new[i] = a[i] + k * a[m-i] (symmetric pairs, scalar).
            #pragma unroll
            for (int i = 1; i < m - i; ++i) {
                float t = A_(i);
                A_(i)     = fmaf(k, A_(m - i), t);
                A_(m - i) = fmaf(k, t, A_(m - i));
            }
            if ((m & 1) == 0 && m >= 2) {
                float t = A_(m >> 1);
                A_(m >> 1) = fmaf(k, t, t);
            }
            A_(m) = k;
        }

        // Write result [K, a1..a64] forward into our (now dead) sA row.
        float* Aw = &sA[tid * RS];
        Aw[0] = sqrtf(E);
        #pragma unroll
        for (int i = 1; i <= M; ++i) Aw[i] = A_(i);
    }
    __syncthreads();

    // Coalesced store from scratch rows.
    #pragma unroll
    for (int i = 0; i < NR; ++i) {
        long long idx = base + (long long)i * BT + tid;
        if (idx < total) {
            int loc = i * BT + tid;
            int b   = loc / NR;
            int c   = loc - b * NR;
            g_out[idx] = sA[b * RS + c];
        }
    }
}

extern "C" void kernel_launch(void* const* d_in, const int* in_sizes, int n_in,
                              void* d_out, int out_size)
{
    const float* r = (const float*)d_in[0];
    float* out = (float*)d_out;
    int nbatch = in_sizes[0] / NR;           // 65536
    int grid = (nbatch + BT - 1) / BT;       // 1024
    levdur_kernel<<<grid, BT>>>(r, out, nbatch);
}

// round 7
// speedup vs baseline: 5.4885x; 5.4885x over previous
#include <cuda_runtime.h>

// Levinson-Durbin, one thread per batch (B=65536, M=64).
// R6 = R1 (best: 25.1us) with the division moved OFF the per-step critical
// path: maintain negInvE = -1/E so k = num * negInvE (4 cyc) instead of
// __fdividef(-num, E) (RCP 16 + muls on the path). The RCP that refreshes
// negInvE for step m+1 overlaps with the update + next dot. E itself is
// tracked multiplicatively (P *= 1-k^2) purely for the final K = sqrt(r0*P).
// Bounds predicates removed (sizes divide exactly). Everything else (shared
// staging, srow reads, 4-acc dot, unconstrained regs) identical to R1.

constexpr int M  = 64;
constexpr int NR = M + 1;   // 65 floats per row
constexpr int BT = 128;     // threads (= batches) per block

__global__ __launch_bounds__(BT)
void levdur_kernel(const float* __restrict__ g_r,
                   float* __restrict__ g_out)
{
    __shared__ float sm[BT * NR];   // 33,280 B
    const int tid = threadIdx.x;
    const long long base = (long long)blockIdx.x * BT * NR;

    // Coalesced load: flat copy of this block's 128 rows (exact fit, no guards).
    #pragma unroll
    for (int i = 0; i < NR; ++i) {
        sm[i * BT + tid] = g_r[base + (long long)i * BT + tid];
    }
    __syncthreads();

    float* r = &sm[tid * NR];   // private row; stride 65 -> conflict-free

    {
        float a[NR];            // a[1..M] in registers (constant indices)
        const float r0 = r[0];
        float negInvE = __fdividef(-1.0f, r0);   // -1/E_0
        float P = 1.0f;                          // prod of (1 - k^2)

        #pragma unroll
        for (int m = 1; m <= M; ++m) {
            // num = r[m] + sum_{j=1}^{m-1} a[j] * r[m-j], 4-way ILP split.
            float acc0 = r[m], acc1 = 0.0f, acc2 = 0.0f, acc3 = 0.0f;
            #pragma unroll
            for (int j = 1; j <= m - 1; ++j) {
                switch ((j - 1) & 3) {
                    case 0: acc0 = fmaf(a[j], r[m - j], acc0); break;
                    case 1: acc1 = fmaf(a[j], r[m - j], acc1); break;
                    case 2: acc2 = fmaf(a[j], r[m - j], acc2); break;
                    default: acc3 = fmaf(a[j], r[m - j], acc3); break;
                }
            }
            float num = (acc0 + acc1) + (acc2 + acc3);

            float k = num * negInvE;             // = -num / E   (4-cyc path)

            // Off-critical-path refresh for next step (hidden under update+dot):
            float c = fmaf(-k, k, 1.0f);         // 1 - k^2
            P *= c;
            negInvE = __fdividef(negInvE, c);    // RCP overlaps with below

            // a_new[j] = a[j] + k * a[m-j], symmetric pairs in place.
            #pragma unroll
            for (int i = 1; i < m - i; ++i) {
                float t = a[i];
                a[i]     = fmaf(k, a[m - i], t);
                a[m - i] = fmaf(k, t, a[m - i]);
            }
            if ((m & 1) == 0 && m >= 2) {        // middle element (m even)
                int h = m >> 1;
                a[h] = fmaf(k, a[h], a[h]);
            }
            a[m] = k;
        }

        // Result into our shared row: [K, a1..aM],  K = sqrt(r0 * prod c).
        r[0] = sqrtf(r0 * P);
        #pragma unroll
        for (int i = 1; i <= M; ++i) r[i] = a[i];
    }
    __syncthreads();

    // Coalesced store (exact fit, no guards).
    #pragma unroll
    for (int i = 0; i < NR; ++i) {
        g_out[base + (long long)i * BT + tid] = sm[i * BT + tid];
    }
}

extern "C" void kernel_launch(void* const* d_in, const int* in_sizes, int n_in,
                              void* d_out, int out_size)
{
    const float* r = (const float*)d_in[0];
    float* out = (float*)d_out;
    int nbatch = in_sizes[0] / NR;           // 65536 (exact multiple of BT)
    int grid = nbatch / BT;                  // 512
    levdur_kernel<<<grid, BT>>>(r, out);
}

// round 8
// speedup vs baseline: 5.4955x; 1.0013x over previous
#include <cuda_runtime.h>

// Levinson-Durbin, one thread per batch (B=65536, M=64).
// R7 = R6 body (negInvE division-off-critical-path; best structure, 144 regs
// natural) with the launch reshaped for a single full wave:
//   BT 128 -> 64, grid 512 -> 1024, __launch_bounds__(64, 7).
// 64 thr x 144 regs = 9216 regs/CTA -> 7 CTAs/SM -> 1036 concurrent CTAs >=
// 1024 grid: no straggler wave (R6 ran 512 CTAs on 444 slots -> 15%+ tail
// idle). Also 3.5 warps/SMSP vs 3. The cap equals the compiler's natural
// allocation for this body, so no spill pressure (unlike R2-R4 caps).

constexpr int M  = 64;
constexpr int NR = M + 1;   // 65 floats per row
constexpr int BT = 64;      // threads (= batches) per block

__global__ __launch_bounds__(BT, 7)
void levdur_kernel(const float* __restrict__ g_r,
                   float* __restrict__ g_out)
{
    __shared__ float sm[BT * NR];   // 16,640 B; 7 CTAs -> 116 KB of 228 KB
    const int tid = threadIdx.x;
    const long long base = (long long)blockIdx.x * BT * NR;

    // Coalesced load: flat copy of this block's 64 rows (exact fit, no guards).
    #pragma unroll
    for (int i = 0; i < NR; ++i) {
        sm[i * BT + tid] = g_r[base + (long long)i * BT + tid];
    }
    __syncthreads();

    float* r = &sm[tid * NR];   // private row; stride 65 -> conflict-free

    {
        float a[NR];            // a[1..M] in registers (constant indices)
        const float r0 = r[0];
        float negInvE = __fdividef(-1.0f, r0);   // -1/E_0
        float P = 1.0f;                          // prod of (1 - k^2)

        #pragma unroll
        for (int m = 1; m <= M; ++m) {
            // num = r[m] + sum_{j=1}^{m-1} a[j] * r[m-j], 4-way ILP split.
            float acc0 = r[m], acc1 = 0.0f, acc2 = 0.0f, acc3 = 0.0f;
            #pragma unroll
            for (int j = 1; j <= m - 1; ++j) {
                switch ((j - 1) & 3) {
                    case 0: acc0 = fmaf(a[j], r[m - j], acc0); break;
                    case 1: acc1 = fmaf(a[j], r[m - j], acc1); break;
                    case 2: acc2 = fmaf(a[j], r[m - j], acc2); break;
                    default: acc3 = fmaf(a[j], r[m - j], acc3); break;
                }
            }
            float num = (acc0 + acc1) + (acc2 + acc3);

            float k = num * negInvE;             // = -num / E   (4-cyc path)

            // Off-critical-path refresh for next step (hidden under update+dot):
            float c = fmaf(-k, k, 1.0f);         // 1 - k^2
            P *= c;
            negInvE = __fdividef(negInvE, c);    // RCP overlaps with below

            // a_new[j] = a[j] + k * a[m-j], symmetric pairs in place.
            #pragma unroll
            for (int i = 1; i < m - i; ++i) {
                float t = a[i];
                a[i]     = fmaf(k, a[m - i], t);
                a[m - i] = fmaf(k, t, a[m - i]);
            }
            if ((m & 1) == 0 && m >= 2) {        // middle element (m even)
                int h = m >> 1;
                a[h] = fmaf(k, a[h], a[h]);
            }
            a[m] = k;
        }

        // Result into our shared row: [K, a1..aM],  K = sqrt(r0 * prod c).
        r[0] = sqrtf(r0 * P);
        #pragma unroll
        for (int i = 1; i <= M; ++i) r[i] = a[i];
    }
    __syncthreads();

    // Coalesced store (exact fit, no guards).
    #pragma unroll
    for (int i = 0; i < NR; ++i) {
        g_out[base + (long long)i * BT + tid] = sm[i * BT + tid];
    }
}

extern "C" void kernel_launch(void* const* d_in, const int* in_sizes, int n_in,
                              void* d_out, int out_size)
{
    const float* r = (const float*)d_in[0];
    float* out = (float*)d_out;
    int nbatch = in_sizes[0] / NR;           // 65536 (exact multiple of BT)
    int grid = nbatch / BT;                  // 1024
    levdur_kernel<<<grid, BT>>>(r, out);
}